// round 9
// baseline (speedup 1.0000x reference)
#include <cuda_runtime.h>
#include <math.h>

#define DFIX  4096
#define GATEB 4096          // gate blocks (one per gated element)

__device__ float    g_gated[8192];
__device__ unsigned g_ready;   // gate completion counter (release/acquire)
__device__ unsigned g_done;    // reset coordinator

__device__ __forceinline__ unsigned ld_acquire_gpu(const unsigned* p) {
    unsigned v;
    asm volatile("ld.acquire.gpu.u32 %0, [%1];" : "=r"(v) : "l"(p) : "memory");
    return v;
}

// ---------------------------------------------------------------------------
// Fused kernel: blocks [0, GATEB) compute gated (W L2-resident across graph
// replays since sim streams memory with .cs); blocks [GATEB, GATEB+N) compute
// sims. Sim blocks issue their 4 DRAM float4 loads BEFORE the gate wait so
// the 256MB stream overlaps the LTS-bound gate.
// Gated reads: PLAIN caching loads (no __ldg/.nc — illegal for data written
// this launch; no __restrict__ — it aliases g_gated). First post-wait access
// per SM misses L1 -> L2 (which holds the released writes); later blocks hit
// L1 with the final value.
// ---------------------------------------------------------------------------
__global__ __launch_bounds__(256, 8)
void fused2_kernel(const float* __restrict__ q,
                   const float* __restrict__ W,
                   const float* __restrict__ b,
                   const float* __restrict__ mem,
                   float* __restrict__ out,
                   int N, int writeMask, int totalBlocks) {
    __shared__ float red[8];
    const int tid  = threadIdx.x;
    const int wid  = tid >> 5;
    const int lane = tid & 31;
    const int bid  = blockIdx.x;

    if (bid < GATEB) {
        // ---------------- gate: one block per output row ----------------
        const int row = bid;
        const float4* w4 = reinterpret_cast<const float4*>(W + (size_t)row * DFIX);
        const float4* q4 = reinterpret_cast<const float4*>(q);

        float s = 0.0f;
        const int base = wid * 128;
        #pragma unroll
        for (int i = 0; i < 4; i++) {
            const int idx = base + lane + i * 32;
            const float4 wv = w4[idx];
            const float4 qv = q4[idx];
            s += wv.x * qv.x + wv.y * qv.y + wv.z * qv.z + wv.w * qv.w;
        }
        #pragma unroll
        for (int o = 16; o > 0; o >>= 1) s += __shfl_xor_sync(0xFFFFFFFFu, s, o);
        if (lane == 0) red[wid] = s;
        __syncthreads();
        if (tid == 0) {
            const float tot = red[0] + red[1] + red[2] + red[3]
                            + red[4] + red[5] + red[6] + red[7];
            const float x = tot + b[row];
            g_gated[row] = 1.0f / (1.0f + expf(-x));
            __threadfence();              // release: gated visible before count
            atomicAdd(&g_ready, 1u);
        }
    } else {
        // ---------------- sim: one block per pattern ---------------------
        const int p = bid - GATEB;
        const float4* m4 = reinterpret_cast<const float4*>(mem + (size_t)p * DFIX);

        // Independent DRAM loads issued before the wait.
        float4 mv0 = __ldcs(&m4[tid]);
        float4 mv1 = __ldcs(&m4[tid + 256]);
        float4 mv2 = __ldcs(&m4[tid + 512]);
        float4 mv3 = __ldcs(&m4[tid + 768]);

        // Acquire-wait for all gate blocks.
        if (tid == 0) {
            while (ld_acquire_gpu(&g_ready) < GATEB) __nanosleep(64);
        }
        __syncthreads();   // publishes thread0's acquire to the block

        const float4* g4 = reinterpret_cast<const float4*>(g_gated);  // no restrict
        const float4 gv0 = g4[tid];
        const float4 gv1 = g4[tid + 256];
        const float4 gv2 = g4[tid + 512];
        const float4 gv3 = g4[tid + 768];

        float s = fabsf(mv0.x - gv0.x) + fabsf(mv0.y - gv0.y)
                + fabsf(mv0.z - gv0.z) + fabsf(mv0.w - gv0.w)
                + fabsf(mv1.x - gv1.x) + fabsf(mv1.y - gv1.y)
                + fabsf(mv1.z - gv1.z) + fabsf(mv1.w - gv1.w)
                + fabsf(mv2.x - gv2.x) + fabsf(mv2.y - gv2.y)
                + fabsf(mv2.z - gv2.z) + fabsf(mv2.w - gv2.w)
                + fabsf(mv3.x - gv3.x) + fabsf(mv3.y - gv3.y)
                + fabsf(mv3.z - gv3.z) + fabsf(mv3.w - gv3.w);
        #pragma unroll
        for (int o = 16; o > 0; o >>= 1) s += __shfl_xor_sync(0xFFFFFFFFu, s, o);
        if (lane == 0) red[wid] = s;
        __syncthreads();
        if (tid == 0) {
            const float tot = red[0] + red[1] + red[2] + red[3]
                            + red[4] + red[5] + red[6] + red[7];
            const float sim = 1.0f - tot * (1.0f / (float)DFIX);
            out[p] = sim;
            if (writeMask) out[N + p] = (sim >= 0.8f) ? 1.0f : 0.0f;
        }
    }

    // ---- reset counters for the next graph replay (last block only) ----
    if (tid == 0) {
        __threadfence();
        if (atomicAdd(&g_done, 1u) == (unsigned)(totalBlocks - 1)) {
            g_ready = 0u;
            g_done  = 0u;
            __threadfence();
        }
    }
}

// ---------------------------------------------------------------------------
// Generic-D fallback (round-1 proven version)
// ---------------------------------------------------------------------------
__global__ void gate_kernel(const float* __restrict__ q, const float* __restrict__ W,
                            const float* __restrict__ b, int D) {
    int warp = (blockIdx.x * blockDim.x + threadIdx.x) >> 5;
    int lane = threadIdx.x & 31;
    if (warp >= D) return;
    const float4* w4 = reinterpret_cast<const float4*>(W + (size_t)warp * D);
    const float4* q4 = reinterpret_cast<const float4*>(q);
    int D4 = D >> 2;
    float s = 0.0f;
    for (int i = lane; i < D4; i += 32) {
        float4 wv = w4[i]; float4 qv = q4[i];
        s += wv.x * qv.x + wv.y * qv.y + wv.z * qv.z + wv.w * qv.w;
    }
    for (int o = 16; o > 0; o >>= 1) s += __shfl_xor_sync(0xFFFFFFFFu, s, o);
    if (lane == 0) { float x = s + b[warp]; g_gated[warp] = 1.0f / (1.0f + expf(-x)); }
}

__global__ void sim_kernel(const float* __restrict__ mem, float* __restrict__ out,
                           int N, int D, int writeMask) {
    extern __shared__ float sgd[];
    int D4 = D >> 2;
    const float4* g4 = reinterpret_cast<const float4*>(g_gated);
    float4* sg4 = reinterpret_cast<float4*>(sgd);
    for (int i = threadIdx.x; i < D4; i += blockDim.x) sg4[i] = g4[i];
    __syncthreads();
    int warp = (blockIdx.x * blockDim.x + threadIdx.x) >> 5;
    int lane = threadIdx.x & 31;
    if (warp >= N) return;
    const float4* m4 = reinterpret_cast<const float4*>(mem + (size_t)warp * D);
    float s = 0.0f;
    for (int i = lane; i < D4; i += 32) {
        float4 mv = m4[i]; float4 gv = sg4[i];
        s += fabsf(mv.x - gv.x) + fabsf(mv.y - gv.y)
           + fabsf(mv.z - gv.z) + fabsf(mv.w - gv.w);
    }
    for (int o = 16; o > 0; o >>= 1) s += __shfl_xor_sync(0xFFFFFFFFu, s, o);
    if (lane == 0) {
        float sim = 1.0f - s / (float)D;
        out[warp] = sim;
        if (writeMask) out[N + warp] = (sim >= 0.8f) ? 1.0f : 0.0f;
    }
}

// ---------------------------------------------------------------------------
extern "C" void kernel_launch(void* const* d_in, const int* in_sizes, int n_in,
                              void* d_out, int out_size) {
    const float* q   = (const float*)d_in[0];
    const float* W   = (const float*)d_in[1];
    const float* b   = (const float*)d_in[2];
    const float* mem = (const float*)d_in[3];
    float* out = (float*)d_out;

    int D = in_sizes[0];
    int N = in_sizes[3] / D;
    int writeMask = (out_size >= 2 * N) ? 1 : 0;

    if (D == DFIX) {
        int totalBlocks = GATEB + N;
        fused2_kernel<<<totalBlocks, 256>>>(q, W, b, mem, out,
                                            N, writeMask, totalBlocks);
    } else {
        int blocks1 = (D + 7) / 8;
        gate_kernel<<<blocks1, 256>>>(q, W, b, D);
        int blocks2 = (N + 7) / 8;
        size_t smem = (size_t)D * sizeof(float);
        sim_kernel<<<blocks2, 256, smem>>>(mem, out, N, D, writeMask);
    }
}

// round 10
// speedup vs baseline: 1.5653x; 1.5653x over previous
#include <cuda_runtime.h>
#include <math.h>

#define DFIX 4096

__device__ float g_gated[8192];

// ---------------------------------------------------------------------------
// Gate: one block per output row (proven R5-R7 config). W stays L2-resident
// across graph replays because sim streams `memory` with .cs => gate runs at
// L2 bandwidth (~5us).
// ---------------------------------------------------------------------------
__global__ __launch_bounds__(256)
void gatep2_kernel(const float* __restrict__ q,
                   const float* __restrict__ W,
                   const float* __restrict__ b) {
    __shared__ float red[8];
    const int row  = blockIdx.x;
    const int wid  = threadIdx.x >> 5;
    const int lane = threadIdx.x & 31;

    const float4* w4 = reinterpret_cast<const float4*>(W + (size_t)row * DFIX);
    const float4* q4 = reinterpret_cast<const float4*>(q);

    float s = 0.0f;
    const int base = wid * 128;
    #pragma unroll
    for (int i = 0; i < 4; i++) {
        const int idx = base + lane + i * 32;
        const float4 wv = w4[idx];
        const float4 qv = q4[idx];
        s += wv.x * qv.x + wv.y * qv.y + wv.z * qv.z + wv.w * qv.w;
    }
    #pragma unroll
    for (int o = 16; o > 0; o >>= 1) s += __shfl_xor_sync(0xFFFFFFFFu, s, o);
    if (lane == 0) red[wid] = s;
    __syncthreads();
    if (threadIdx.x == 0) {
        const float tot = red[0] + red[1] + red[2] + red[3]
                        + red[4] + red[5] + red[6] + red[7];
        const float x = tot + b[row];
        g_gated[row] = 1.0f / (1.0f + expf(-x));
    }
}

// ---------------------------------------------------------------------------
// Sim (PDL secondary): block-per-pattern, proven R7 body. Issues its 4
// independent float4 DRAM loads BEFORE cudaGridDependencySynchronize() so
// the 256MB stream overlaps the tail of the gate kernel; reads gated only
// after the HW grid dependency resolves (gate grid complete => writes
// visible; gated is read-only within THIS launch, so __ldg is legal).
// ---------------------------------------------------------------------------
__global__ __launch_bounds__(256, 8)
void sim3_kernel(const float* __restrict__ mem,
                 const float* __restrict__ gated,
                 float* __restrict__ out,
                 int N, int writeMask) {
    __shared__ float red[8];
    const int p    = blockIdx.x;
    const int tid  = threadIdx.x;
    const int wid  = tid >> 5;
    const int lane = tid & 31;

    const float4* m4 = reinterpret_cast<const float4*>(mem + (size_t)p * DFIX);

    // Independent DRAM loads, issued before the grid dependency resolves.
    const float4 mv0 = __ldcs(&m4[tid]);
    const float4 mv1 = __ldcs(&m4[tid + 256]);
    const float4 mv2 = __ldcs(&m4[tid + 512]);
    const float4 mv3 = __ldcs(&m4[tid + 768]);

#if __CUDA_ARCH__ >= 900
    cudaGridDependencySynchronize();   // HW wait: gate grid complete + visible
#endif

    const float4* g4 = reinterpret_cast<const float4*>(gated);
    const float4 gv0 = __ldg(&g4[tid]);
    const float4 gv1 = __ldg(&g4[tid + 256]);
    const float4 gv2 = __ldg(&g4[tid + 512]);
    const float4 gv3 = __ldg(&g4[tid + 768]);

    float s = fabsf(mv0.x - gv0.x) + fabsf(mv0.y - gv0.y)
            + fabsf(mv0.z - gv0.z) + fabsf(mv0.w - gv0.w)
            + fabsf(mv1.x - gv1.x) + fabsf(mv1.y - gv1.y)
            + fabsf(mv1.z - gv1.z) + fabsf(mv1.w - gv1.w)
            + fabsf(mv2.x - gv2.x) + fabsf(mv2.y - gv2.y)
            + fabsf(mv2.z - gv2.z) + fabsf(mv2.w - gv2.w)
            + fabsf(mv3.x - gv3.x) + fabsf(mv3.y - gv3.y)
            + fabsf(mv3.z - gv3.z) + fabsf(mv3.w - gv3.w);
    #pragma unroll
    for (int o = 16; o > 0; o >>= 1) s += __shfl_xor_sync(0xFFFFFFFFu, s, o);
    if (lane == 0) red[wid] = s;
    __syncthreads();
    if (tid == 0) {
        const float tot = red[0] + red[1] + red[2] + red[3]
                        + red[4] + red[5] + red[6] + red[7];
        const float sim = 1.0f - tot * (1.0f / (float)DFIX);
        out[p] = sim;
        if (writeMask) out[N + p] = (sim >= 0.8f) ? 1.0f : 0.0f;
    }
}

// ---------------------------------------------------------------------------
// Generic-D fallback (round-1 proven version)
// ---------------------------------------------------------------------------
__global__ void gate_kernel(const float* __restrict__ q, const float* __restrict__ W,
                            const float* __restrict__ b, int D) {
    int warp = (blockIdx.x * blockDim.x + threadIdx.x) >> 5;
    int lane = threadIdx.x & 31;
    if (warp >= D) return;
    const float4* w4 = reinterpret_cast<const float4*>(W + (size_t)warp * D);
    const float4* q4 = reinterpret_cast<const float4*>(q);
    int D4 = D >> 2;
    float s = 0.0f;
    for (int i = lane; i < D4; i += 32) {
        float4 wv = w4[i]; float4 qv = q4[i];
        s += wv.x * qv.x + wv.y * qv.y + wv.z * qv.z + wv.w * qv.w;
    }
    for (int o = 16; o > 0; o >>= 1) s += __shfl_xor_sync(0xFFFFFFFFu, s, o);
    if (lane == 0) { float x = s + b[warp]; g_gated[warp] = 1.0f / (1.0f + expf(-x)); }
}

__global__ void sim_kernel(const float* __restrict__ mem, float* __restrict__ out,
                           int N, int D, int writeMask) {
    extern __shared__ float sgd[];
    int D4 = D >> 2;
    const float4* g4 = reinterpret_cast<const float4*>(g_gated);
    float4* sg4 = reinterpret_cast<float4*>(sgd);
    for (int i = threadIdx.x; i < D4; i += blockDim.x) sg4[i] = g4[i];
    __syncthreads();
    int warp = (blockIdx.x * blockDim.x + threadIdx.x) >> 5;
    int lane = threadIdx.x & 31;
    if (warp >= N) return;
    const float4* m4 = reinterpret_cast<const float4*>(mem + (size_t)warp * D);
    float s = 0.0f;
    for (int i = lane; i < D4; i += 32) {
        float4 mv = m4[i]; float4 gv = sg4[i];
        s += fabsf(mv.x - gv.x) + fabsf(mv.y - gv.y)
           + fabsf(mv.z - gv.z) + fabsf(mv.w - gv.w);
    }
    for (int o = 16; o > 0; o >>= 1) s += __shfl_xor_sync(0xFFFFFFFFu, s, o);
    if (lane == 0) {
        float sim = 1.0f - s / (float)D;
        out[warp] = sim;
        if (writeMask) out[N + warp] = (sim >= 0.8f) ? 1.0f : 0.0f;
    }
}

// ---------------------------------------------------------------------------
extern "C" void kernel_launch(void* const* d_in, const int* in_sizes, int n_in,
                              void* d_out, int out_size) {
    const float* q   = (const float*)d_in[0];
    const float* W   = (const float*)d_in[1];
    const float* b   = (const float*)d_in[2];
    const float* mem = (const float*)d_in[3];
    float* out = (float*)d_out;

    int D = in_sizes[0];
    int N = in_sizes[3] / D;
    int writeMask = (out_size >= 2 * N) ? 1 : 0;

    if (D == DFIX) {
        const float* gated_ptr = nullptr;
        cudaGetSymbolAddress((void**)&gated_ptr, g_gated);

        gatep2_kernel<<<DFIX, 256>>>(q, W, b);

        // Sim as PDL secondary: blocks launch while gate still runs, issue
        // their DRAM loads, then HW-wait on the gate grid.
        cudaLaunchConfig_t cfg = {};
        cfg.gridDim  = dim3((unsigned)N);
        cfg.blockDim = dim3(256);
        cudaLaunchAttribute attrs[1];
        attrs[0].id = cudaLaunchAttributeProgrammaticStreamSerialization;
        attrs[0].val.programmaticStreamSerializationAllowed = 1;
        cfg.attrs = attrs;
        cfg.numAttrs = 1;
        cudaError_t e = cudaLaunchKernelEx(&cfg, sim3_kernel,
                                           mem, gated_ptr, out, N, writeMask);
        if (e != cudaSuccess) {
            // Fallback: plain serialized launch (R7 behavior).
            sim3_kernel<<<N, 256>>>(mem, gated_ptr, out, N, writeMask);
        }
    } else {
        int blocks1 = (D + 7) / 8;
        gate_kernel<<<blocks1, 256>>>(q, W, b, D);
        int blocks2 = (N + 7) / 8;
        size_t smem = (size_t)D * sizeof(float);
        sim_kernel<<<blocks2, 256, smem>>>(mem, out, N, D, writeMask);
    }
}